// round 11
// baseline (speedup 1.0000x reference)
#include <cuda_runtime.h>
#include <cuda_bf16.h>
#include <cstdint>
#include <cstddef>

#define NN 50000
#define NE 600000
#define D  128
#define NTILES ((NN + 127) / 128)   // 391
#define THREADS 1024
#define SCANB ((NN + 255) / 256)    // 196
#define NCTAS 148

#define PB 272
#define XH_OFF 0
#define XL_OFF 34816
#define WSH_OFF 69632
#define WSL_OFF 104448
#define WNH_OFF 139264
#define WNL_OFF 174080
#define EIDX_OFF 208896
#define EIDX_CAP 4096
#define SMEM_BYTES (208896 + 16384)
#define EPI_PITCH 136

// ---------------------------------------------------------------------------
__device__ float g_h1[(size_t)NN * D];
__device__ float g_h2[(size_t)NN * D];
__device__ int   g_degi[NN];
__device__ float g_dinv[NN];
__device__ int   g_rowptr[NN + 1];
__device__ int   g_cursor[NN];
__device__ int   g_csrc[NE];
__device__ unsigned long long g_desc[SCANB];
__device__ unsigned g_barcnt;
__device__ unsigned g_barphase;
__device__ int g_tilectr[3];
__device__ __nv_bfloat16 g_Wth[6 * D * D];
__device__ __nv_bfloat16 g_Wtl[6 * D * D];

// ---------------------------------------------------------------------------
__device__ __forceinline__ void ldsm4(uint32_t* r, uint32_t addr) {
    asm volatile("ldmatrix.sync.aligned.m8n8.x4.shared.b16 {%0,%1,%2,%3}, [%4];"
                 : "=r"(r[0]), "=r"(r[1]), "=r"(r[2]), "=r"(r[3]) : "r"(addr));
}

__device__ __forceinline__ void mma16816(float* c, const uint32_t* a, const uint32_t* b) {
    asm volatile(
        "mma.sync.aligned.m16n8k16.row.col.f32.bf16.bf16.f32 "
        "{%0,%1,%2,%3}, {%4,%5,%6,%7}, {%8,%9}, {%0,%1,%2,%3};"
        : "+f"(c[0]), "+f"(c[1]), "+f"(c[2]), "+f"(c[3])
        : "r"(a[0]), "r"(a[1]), "r"(a[2]), "r"(a[3]), "r"(b[0]), "r"(b[1]));
}

__device__ __forceinline__ uint32_t smem_u32(const void* p) {
    return (uint32_t)__cvta_generic_to_shared(p);
}

__device__ __forceinline__ uint32_t split2(float x, float y, uint32_t& lo) {
    __nv_bfloat162 h = __float22bfloat162_rn(make_float2(x, y));
    float2 hf = __bfloat1622float2(h);
    __nv_bfloat162 l = __float22bfloat162_rn(make_float2(x - hf.x, y - hf.y));
    lo = reinterpret_cast<uint32_t&>(l);
    return reinterpret_cast<uint32_t&>(h);
}

__device__ __forceinline__ void gbar512() {
    asm volatile("bar.sync 1, 512;" ::: "memory");
}

__device__ __forceinline__ void grid_barrier(unsigned gen) {
    __syncthreads();
    if (threadIdx.x == 0) {
        __threadfence();
        unsigned old = atomicAdd(&g_barcnt, 1u);
        if (old == gen * NCTAS - 1u) {
            atomicExch(&g_barphase, gen);
        } else {
            while (atomicAdd(&g_barphase, 0u) < gen) {}
        }
        __threadfence();
    }
    __syncthreads();
}

// ---------------------------------------------------------------------------
__global__ void k_count_wprep(const int* __restrict__ dst,
                              const float* W0, const float* W1, const float* W2,
                              const float* W3, const float* W4, const float* W5) {
    int i = blockIdx.x * blockDim.x + threadIdx.x;
    if (i < NE / 2) {
        int2 d = ((const int2*)dst)[i];
        atomicAdd(&g_degi[d.x], 1);
        atomicAdd(&g_degi[d.y], 1);
    }
    if (i < 6 * D * D) {
        int w = i >> 14;
        int r = i & 16383;
        int n = r >> 7, k = r & 127;
        const float* W;
        switch (w) {
            case 0: W = W0; break; case 1: W = W1; break; case 2: W = W2; break;
            case 3: W = W3; break; case 4: W = W4; break; default: W = W5; break;
        }
        float v = W[k * D + n];
        __nv_bfloat16 h = __float2bfloat16_rn(v);
        float res = v - __bfloat162float(h);
        g_Wth[i] = h;
        g_Wtl[i] = __float2bfloat16_rn(res);
    }
}

__global__ void __launch_bounds__(256) k_scan() {
    __shared__ int ws[8];
    __shared__ int s_boff;
    const int b = blockIdx.x;
    const int i = b * 256 + threadIdx.x;
    const int lane = threadIdx.x & 31, wid = threadIdx.x >> 5;

    int v = (i < NN) ? g_degi[i] : 0;
    int x = v;
#pragma unroll
    for (int o = 1; o < 32; o <<= 1) {
        int y = __shfl_up_sync(0xffffffffu, x, o);
        if (lane >= o) x += y;
    }
    if (lane == 31) ws[wid] = x;
    __syncthreads();
    if (wid == 0 && lane < 8) {
        int w = ws[lane];
#pragma unroll
        for (int o = 1; o < 8; o <<= 1) {
            int y = __shfl_up_sync(0xffu, w, o);
            if (lane >= o) w += y;
        }
        ws[lane] = w;
    }
    __syncthreads();
    int off = (wid > 0) ? ws[wid - 1] : 0;
    int S = ws[7];

    if (threadIdx.x == 0) {
        int boff = 0;
        if (b == 0) {
            atomicExch(&g_desc[0], (2ULL << 32) | (unsigned)S);
        } else {
            atomicExch(&g_desc[b], (1ULL << 32) | (unsigned)S);
            int j = b - 1;
            long long sum = 0;
            while (true) {
                unsigned long long d = atomicAdd(&g_desc[j], 0ULL);
                unsigned f = (unsigned)(d >> 32);
                if (f == 0) continue;
                sum += (unsigned)(d & 0xffffffffULL);
                if (f == 2) break;
                j--;
            }
            boff = (int)sum;
            atomicExch(&g_desc[b], (2ULL << 32) | (unsigned)(boff + S));
        }
        s_boff = boff;
    }
    __syncthreads();
    int boff = s_boff;
    if (i < NN) {
        int ex = boff + off + x - v;
        g_rowptr[i] = ex;
        g_cursor[i] = ex;
        g_dinv[i] = 1.0f / fmaxf((float)v, 1.0f);
    }
    if (b == 0 && threadIdx.x == 0) g_rowptr[NN] = NE;
}

__global__ void k_fill(const int* __restrict__ src, const int* __restrict__ dst) {
    int i = blockIdx.x * blockDim.x + threadIdx.x;
    if (i < NE / 2) {
        int2 d = ((const int2*)dst)[i];
        int2 s = ((const int2*)src)[i];
        int p0 = atomicAdd(&g_cursor[d.x], 1);
        g_csrc[p0] = s.x;
        int p1 = atomicAdd(&g_cursor[d.y], 1);
        g_csrc[p1] = s.y;
    }
    if (i < NN) g_degi[i] = 0;
    if (i < SCANB) g_desc[i] = 0ULL;
    if (i < 3) g_tilectr[i] = 0;
    if (i == 3) { g_barcnt = 0u; g_barphase = 0u; }
}

// ---------------------------------------------------------------------------
// one ks-step for a 32x32 warp tile, phased frag loading (peak 24 frag regs)
// ---------------------------------------------------------------------------
__device__ __forceinline__ void gemm3_step(float acc[2][4][4],
                                           uint32_t aXH, uint32_t aXL,
                                           uint32_t aWH, uint32_t aWL,
                                           uint32_t aoff0, uint32_t aoff1,
                                           uint32_t boff0, uint32_t boff1,
                                           uint32_t kb) {
    uint32_t ah[8], bx[8], al[8];
    ldsm4(ah + 0, aXH + aoff0 + kb);
    ldsm4(ah + 4, aXH + aoff1 + kb);
    ldsm4(bx + 0, aWH + boff0 + kb);
    ldsm4(bx + 4, aWH + boff1 + kb);
#pragma unroll
    for (int i = 0; i < 2; i++)
#pragma unroll
        for (int j = 0; j < 4; j++)
            mma16816(acc[i][j], ah + i * 4, bx + (j >> 1) * 4 + (j & 1) * 2);
    ldsm4(al + 0, aXL + aoff0 + kb);
    ldsm4(al + 4, aXL + aoff1 + kb);
#pragma unroll
    for (int i = 0; i < 2; i++)
#pragma unroll
        for (int j = 0; j < 4; j++)
            mma16816(acc[i][j], al + i * 4, bx + (j >> 1) * 4 + (j & 1) * 2);
    ldsm4(bx + 0, aWL + boff0 + kb);
    ldsm4(bx + 4, aWL + boff1 + kb);
#pragma unroll
    for (int i = 0; i < 2; i++)
#pragma unroll
        for (int j = 0; j < 4; j++)
            mma16816(acc[i][j], ah + i * 4, bx + (j >> 1) * 4 + (j & 1) * 2);
}

// gather one CSR row with compile-time MLP
template <int MLP>
__device__ __forceinline__ float4 gather_row(const float* __restrict__ hin,
                                             const int* __restrict__ idxp,
                                             int bgn, int cnt, int koff) {
    float4 a = make_float4(0.f, 0.f, 0.f, 0.f);
    int e = 0;
    if (MLP >= 8) {
        for (; e + 8 <= cnt; e += 8) {
            float4 v0 = *(const float4*)(hin + (size_t)idxp[bgn + e + 0] * D + koff);
            float4 v1 = *(const float4*)(hin + (size_t)idxp[bgn + e + 1] * D + koff);
            float4 v2 = *(const float4*)(hin + (size_t)idxp[bgn + e + 2] * D + koff);
            float4 v3 = *(const float4*)(hin + (size_t)idxp[bgn + e + 3] * D + koff);
            float4 v4 = *(const float4*)(hin + (size_t)idxp[bgn + e + 4] * D + koff);
            float4 v5 = *(const float4*)(hin + (size_t)idxp[bgn + e + 5] * D + koff);
            float4 v6 = *(const float4*)(hin + (size_t)idxp[bgn + e + 6] * D + koff);
            float4 v7 = *(const float4*)(hin + (size_t)idxp[bgn + e + 7] * D + koff);
            a.x += v0.x + v1.x + v2.x + v3.x + v4.x + v5.x + v6.x + v7.x;
            a.y += v0.y + v1.y + v2.y + v3.y + v4.y + v5.y + v6.y + v7.y;
            a.z += v0.z + v1.z + v2.z + v3.z + v4.z + v5.z + v6.z + v7.z;
            a.w += v0.w + v1.w + v2.w + v3.w + v4.w + v5.w + v6.w + v7.w;
        }
    }
    for (; e + 4 <= cnt; e += 4) {
        float4 v0 = *(const float4*)(hin + (size_t)idxp[bgn + e + 0] * D + koff);
        float4 v1 = *(const float4*)(hin + (size_t)idxp[bgn + e + 1] * D + koff);
        float4 v2 = *(const float4*)(hin + (size_t)idxp[bgn + e + 2] * D + koff);
        float4 v3 = *(const float4*)(hin + (size_t)idxp[bgn + e + 3] * D + koff);
        a.x += v0.x + v1.x + v2.x + v3.x;
        a.y += v0.y + v1.y + v2.y + v3.y;
        a.z += v0.z + v1.z + v2.z + v3.z;
        a.w += v0.w + v1.w + v2.w + v3.w;
    }
    if (e + 2 <= cnt) {
        float4 v0 = *(const float4*)(hin + (size_t)idxp[bgn + e + 0] * D + koff);
        float4 v1 = *(const float4*)(hin + (size_t)idxp[bgn + e + 1] * D + koff);
        a.x += v0.x + v1.x; a.y += v0.y + v1.y;
        a.z += v0.z + v1.z; a.w += v0.w + v1.w;
        e += 2;
    }
    if (e < cnt) {
        float4 v0 = *(const float4*)(hin + (size_t)idxp[bgn + e] * D + koff);
        a.x += v0.x; a.y += v0.y; a.z += v0.z; a.w += v0.w;
    }
    return a;
}

// ---------------------------------------------------------------------------
// persistent fused 3-layer kernel — warp-specialized: 16 MMA + 16 gather warps
// ---------------------------------------------------------------------------
__global__ void __launch_bounds__(THREADS, 1)
k_layers(const float* __restrict__ feat,
         const float* __restrict__ b1,
         const float* __restrict__ b2,
         const float* __restrict__ b3,
         float* __restrict__ out) {
    extern __shared__ __align__(16) char smem[];
    __shared__ int sRp[129];
    __shared__ int s_tile, s_tile2;
    int* sEidx = (int*)(smem + EIDX_OFF);

    const int tid  = threadIdx.x;
    const int wid  = tid >> 5;
    const int lane = tid & 31;
    const bool isMMA = (wid < 16);
    const int mw = wid >> 2;          // MMA: 0..3 (rows mw*32)
    const int nw = wid & 3;           // MMA: 0..3 (cols nw*32)
    const int gtid = tid - 512;       // gather thread id (0..511)
    const uint32_t sb = smem_u32(smem);

    const int quad = lane >> 3, rin = lane & 7;
    const uint32_t aoff0 = (uint32_t)((mw * 32 + (quad & 1) * 8 + rin) * PB + (quad >> 1) * 16);
    const uint32_t aoff1 = aoff0 + 16 * PB;
    const uint32_t boff0 = (uint32_t)((nw * 32 + (quad >> 1) * 8 + rin) * PB + (quad & 1) * 16);
    const uint32_t boff1 = boff0 + 16 * PB;
    const int koff = lane << 2;

    for (int L = 0; L < 3; L++) {
        const float* hin  = (L == 0) ? feat : ((L == 1) ? g_h1 : g_h2);
        float* hout       = (L == 0) ? g_h1 : ((L == 1) ? g_h2 : out);
        const float* bias = (L == 0) ? b1 : ((L == 1) ? b2 : b3);
        const bool relu = (L < 2);
        const __nv_bfloat16* Wh = g_Wth + (size_t)L * 2 * D * D;
        const __nv_bfloat16* Wl = g_Wtl + (size_t)L * 2 * D * D;

        // stage this layer's 4 weight buffers (all warps)
        for (int c = tid; c < 2048; c += THREADS) {
            int row = c >> 4, k8 = (c & 15) << 3;
            uint32_t doff = row * PB + k8 * 2;
            *(uint4*)(smem + WSH_OFF + doff) = *(const uint4*)(Wh + row * D + k8);
            *(uint4*)(smem + WSL_OFF + doff) = *(const uint4*)(Wl + row * D + k8);
            *(uint4*)(smem + WNH_OFF + doff) = *(const uint4*)(Wh + 16384 + row * D + k8);
            *(uint4*)(smem + WNL_OFF + doff) = *(const uint4*)(Wl + 16384 + row * D + k8);
        }
        float2 bj[4];
        if (isMMA) {
#pragma unroll
            for (int j = 0; j < 4; j++)
                bj[j] = *(const float2*)(bias + nw * 32 + j * 8 + 2 * (lane & 3));
        }

        // gather-warp persistent state
        int e0base = 0;
        bool inSmem = true;
        float dvl = 0.f;

        // prologue: first tile
        if (tid == 512) s_tile = atomicAdd(&g_tilectr[L], 1);
        __syncthreads();
        int tile = s_tile;
        if (!isMMA) {
            const bool tv = (tile < NTILES);
            const int nb = tile * 128;
            if (tv) {
#pragma unroll
                for (int it = 0; it < 8; it++) {
                    int c = gtid + it * 512;
                    int row = c >> 5, kc = (c & 31) << 2;
                    int n = nb + row;
                    float4 v = make_float4(0.f, 0.f, 0.f, 0.f);
                    if (n < NN) v = *(const float4*)(hin + (size_t)n * D + kc);
                    uint2 hi, lo;
                    hi.x = split2(v.x, v.y, lo.x);
                    hi.y = split2(v.z, v.w, lo.y);
                    uint32_t doff = row * PB + kc * 2;
                    *(uint2*)(smem + XH_OFF + doff) = hi;
                    *(uint2*)(smem + XL_OFF + doff) = lo;
                }
                if (gtid <= 128) {
                    int n = nb + gtid;
                    sRp[gtid] = g_rowptr[(n < NN) ? n : NN];
                }
                if (lane < 8) {
                    int n = nb + (wid - 16) * 8 + lane;
                    dvl = (n < NN) ? g_dinv[n] : 0.f;
                }
            }
            gbar512();
            if (tv) {
                e0base = sRp[0];
                int ecnt = sRp[128] - e0base;
                inSmem = (ecnt <= EIDX_CAP);
                if (inSmem)
                    for (int idx = gtid; idx < ecnt; idx += 512)
                        sEidx[idx] = g_csrc[e0base + idx];
            }
        }
        __syncthreads();

        while (tile < NTILES) {
            const int nbase = tile * 128;
            float acc[2][4][4];
            uint2 mh[8], ml[8];
            float4 xv[8];
            int ntile = NTILES;
            bool nvalid = false;

            // ================= PHASE A: GEMM1 || gather M =================
            if (tid == 512) s_tile2 = atomicAdd(&g_tilectr[L], 1);
            if (isMMA) {
#pragma unroll
                for (int i = 0; i < 2; i++)
#pragma unroll
                    for (int j = 0; j < 4; j++)
#pragma unroll
                        for (int r = 0; r < 4; r++) acc[i][j][r] = 0.f;
#pragma unroll
                for (int ks = 0; ks < 8; ks++)
                    gemm3_step(acc, sb + XH_OFF, sb + XL_OFF, sb + WSH_OFF, sb + WSL_OFF,
                               aoff0, aoff1, boff0, boff1, ks * 32);
            } else {
                const int r0 = (wid - 16) << 3;
                const int* __restrict__ idxp = inSmem ? sEidx : (g_csrc + e0base);
#pragma unroll
                for (int i = 0; i < 6; i++) {
                    int bgn = sRp[r0 + i] - e0base;
                    int cnt = sRp[r0 + i + 1] - e0base - bgn;
                    float4 a = gather_row<8>(hin, idxp, bgn, cnt, koff);
                    float di = __shfl_sync(0xffffffffu, dvl, i);
                    mh[i].x = split2(a.x * di, a.y * di, ml[i].x);
                    mh[i].y = split2(a.z * di, a.w * di, ml[i].y);
                }
#pragma unroll
                for (int i = 6; i < 8; i++) {
                    int bgn = sRp[r0 + i] - e0base;
                    int cnt = sRp[r0 + i + 1] - e0base - bgn;
                    float4 a = gather_row<4>(hin, idxp, bgn, cnt, koff);
                    float di = __shfl_sync(0xffffffffu, dvl, i);
                    mh[i].x = split2(a.x * di, a.y * di, ml[i].x);
                    mh[i].y = split2(a.z * di, a.w * di, ml[i].y);
                }
            }
            __syncthreads();

            // ================= PHASE B: STS M rows =================
            if (!isMMA) {
                const int r0 = (wid - 16) << 3;
#pragma unroll
                for (int i = 0; i < 8; i++) {
                    uint32_t doff = (r0 + i) * PB + lane * 8;
                    *(uint2*)(smem + XH_OFF + doff) = mh[i];
                    *(uint2*)(smem + XL_OFF + doff) = ml[i];
                }
            }
            __syncthreads();

            // ================= PHASE C: GEMM2 || prefetch next tile =======
            if (isMMA) {
#pragma unroll
                for (int ks = 0; ks < 8; ks++)
                    gemm3_step(acc, sb + XH_OFF, sb + XL_OFF, sb + WNH_OFF, sb + WNL_OFF,
                               aoff0, aoff1, boff0, boff1, ks * 32);
            } else {
                ntile = s_tile2;
                nvalid = (ntile < NTILES);
                const int nb2 = ntile * 128;
#pragma unroll
                for (int it = 0; it < 8; it++) {
                    int c = gtid + it * 512;
                    int row = c >> 5, kc = (c & 31) << 2;
                    int n = nb2 + row;
                    xv[it] = make_float4(0.f, 0.f, 0.f, 0.f);
                    if (nvalid && n < NN)
                        xv[it] = *(const float4*)(hin + (size_t)n * D + kc);
                }
                if (gtid <= 128) {
                    int n = nb2 + gtid;
                    sRp[gtid] = nvalid ? g_rowptr[(n < NN) ? n : NN] : 0;
                }
                if (lane < 8) {
                    int n = nb2 + (wid - 16) * 8 + lane;
                    dvl = (nvalid && n < NN) ? g_dinv[n] : 0.f;
                }
                gbar512();
                if (nvalid) {
                    e0base = sRp[0];
                    int ecnt = sRp[128] - e0base;
                    inSmem = (ecnt <= EIDX_CAP);
                    if (inSmem)
                        for (int idx = gtid; idx < ecnt; idx += 512)
                            sEidx[idx] = g_csrc[e0base + idx];
                }
            }
            __syncthreads();

            // ================= PHASE D: epilogue STS =================
            float* sepi = (float*)(smem + XH_OFF);
            if (isMMA) {
#pragma unroll
                for (int i = 0; i < 2; i++) {
                    int r0e = mw * 32 + i * 16 + (lane >> 2);
#pragma unroll
                    for (int j = 0; j < 4; j++) {
                        int col = nw * 32 + j * 8 + 2 * (lane & 3);
                        float2 v0, v1;
                        v0.x = acc[i][j][0] + bj[j].x;
                        v0.y = acc[i][j][1] + bj[j].y;
                        v1.x = acc[i][j][2] + bj[j].x;
                        v1.y = acc[i][j][3] + bj[j].y;
                        if (relu) {
                            v0.x = fmaxf(v0.x, 0.f); v0.y = fmaxf(v0.y, 0.f);
                            v1.x = fmaxf(v1.x, 0.f); v1.y = fmaxf(v1.y, 0.f);
                        }
                        *(float2*)(sepi + r0e * EPI_PITCH + col) = v0;
                        *(float2*)(sepi + (r0e + 8) * EPI_PITCH + col) = v1;
                    }
                }
            }
            __syncthreads();

            // ================= PHASE E: STG epilogue (all warps) ==========
#pragma unroll
            for (int it = 0; it < 4; it++) {
                int c = tid + it * THREADS;
                int row = c >> 5, k0 = (c & 31) << 2;
                int n = nbase + row;
                if (n < NN) {
                    float4 v = *(const float4*)(sepi + row * EPI_PITCH + k0);
                    *(float4*)(hout + (size_t)n * D + k0) = v;
                }
            }
            __syncthreads();

            // ================= PHASE F: STS next X =================
            if (!isMMA && nvalid) {
#pragma unroll
                for (int it = 0; it < 8; it++) {
                    int c = gtid + it * 512;
                    int row = c >> 5, kc = (c & 31) << 2;
                    uint2 hi, lo;
                    hi.x = split2(xv[it].x, xv[it].y, lo.x);
                    hi.y = split2(xv[it].z, xv[it].w, lo.y);
                    uint32_t doff = row * PB + kc * 2;
                    *(uint2*)(smem + XH_OFF + doff) = hi;
                    *(uint2*)(smem + XL_OFF + doff) = lo;
                }
            }
            tile = s_tile2;
            __syncthreads();
        }

        if (L < 2) grid_barrier(L + 1);
    }
}

// ---------------------------------------------------------------------------
extern "C" void kernel_launch(void* const* d_in, const int* in_sizes, int n_in,
                              void* d_out, int out_size) {
    const float* feat = (const float*)d_in[0];
    const int* src = (const int*)d_in[1];
    const int* dst = (const int*)d_in[2];
    const float* Ws1 = (const float*)d_in[3];
    const float* Wn1 = (const float*)d_in[4];
    const float* b1  = (const float*)d_in[5];
    const float* Ws2 = (const float*)d_in[6];
    const float* Wn2 = (const float*)d_in[7];
    const float* b2  = (const float*)d_in[8];
    const float* Ws3 = (const float*)d_in[9];
    const float* Wn3 = (const float*)d_in[10];
    const float* b3  = (const float*)d_in[11];
    float* out = (float*)d_out;

    cudaFuncSetAttribute(k_layers, cudaFuncAttributeMaxDynamicSharedMemorySize, SMEM_BYTES);

    const int EBLK = (NE / 2 + 255) / 256;

    k_count_wprep<<<EBLK, 256>>>(dst, Ws1, Wn1, Ws2, Wn2, Ws3, Wn3);
    k_scan<<<SCANB, 256>>>();
    k_fill<<<EBLK, 256>>>(src, dst);
    k_layers<<<NCTAS, THREADS, SMEM_BYTES>>>(feat, b1, b2, b3, out);
}

// round 12
// speedup vs baseline: 1.6828x; 1.6828x over previous
#include <cuda_runtime.h>
#include <cuda_bf16.h>
#include <cstdint>
#include <cstddef>

#define NN 50000
#define NE 600000
#define D  128
#define NTILES ((NN + 127) / 128)   // 391
#define THREADS 1024
#define SCANB ((NN + 255) / 256)    // 196
#define NCTAS 148

#define PB 272
#define XH_OFF 0
#define XL_OFF 34816
#define WSH_OFF 69632
#define WSL_OFF 104448
#define WNH_OFF 139264
#define WNL_OFF 174080
#define EIDX_OFF 208896
#define EIDX_CAP 4096
#define SMEM_BYTES (208896 + 16384)
#define EPI_PITCH 136

// ---------------------------------------------------------------------------
__device__ float g_h1[(size_t)NN * D];
__device__ float g_h2[(size_t)NN * D];
__device__ int   g_degi[NN];
__device__ float g_dinv[NN];
__device__ int   g_rowptr[NN + 1];
__device__ int   g_cursor[NN];
__device__ int   g_csrc[NE];
__device__ unsigned long long g_desc[SCANB];
__device__ unsigned g_barcnt;
__device__ unsigned g_barphase;
__device__ int g_tilectr[3];
__device__ __nv_bfloat16 g_Wth[6 * D * D];
__device__ __nv_bfloat16 g_Wtl[6 * D * D];

// ---------------------------------------------------------------------------
__device__ __forceinline__ void ldsm4(uint32_t* r, uint32_t addr) {
    asm volatile("ldmatrix.sync.aligned.m8n8.x4.shared.b16 {%0,%1,%2,%3}, [%4];"
                 : "=r"(r[0]), "=r"(r[1]), "=r"(r[2]), "=r"(r[3]) : "r"(addr));
}

__device__ __forceinline__ void mma16816(float* c, const uint32_t* a, const uint32_t* b) {
    asm volatile(
        "mma.sync.aligned.m16n8k16.row.col.f32.bf16.bf16.f32 "
        "{%0,%1,%2,%3}, {%4,%5,%6,%7}, {%8,%9}, {%0,%1,%2,%3};"
        : "+f"(c[0]), "+f"(c[1]), "+f"(c[2]), "+f"(c[3])
        : "r"(a[0]), "r"(a[1]), "r"(a[2]), "r"(a[3]), "r"(b[0]), "r"(b[1]));
}

__device__ __forceinline__ uint32_t smem_u32(const void* p) {
    return (uint32_t)__cvta_generic_to_shared(p);
}

__device__ __forceinline__ void cpasync4(uint32_t saddr, const void* gaddr) {
    asm volatile("cp.async.ca.shared.global [%0], [%1], 4;"
                 :: "r"(saddr), "l"(gaddr) : "memory");
}
__device__ __forceinline__ void cpasync_commit() {
    asm volatile("cp.async.commit_group;" ::: "memory");
}
__device__ __forceinline__ void cpasync_wait0() {
    asm volatile("cp.async.wait_group 0;" ::: "memory");
}

__device__ __forceinline__ uint32_t split2(float x, float y, uint32_t& lo) {
    __nv_bfloat162 h = __float22bfloat162_rn(make_float2(x, y));
    float2 hf = __bfloat1622float2(h);
    __nv_bfloat162 l = __float22bfloat162_rn(make_float2(x - hf.x, y - hf.y));
    lo = reinterpret_cast<uint32_t&>(l);
    return reinterpret_cast<uint32_t&>(h);
}

__device__ __forceinline__ void grid_barrier(unsigned gen) {
    __syncthreads();
    if (threadIdx.x == 0) {
        __threadfence();
        unsigned old = atomicAdd(&g_barcnt, 1u);
        if (old == gen * NCTAS - 1u) {
            atomicExch(&g_barphase, gen);
        } else {
            while (atomicAdd(&g_barphase, 0u) < gen) {}
        }
        __threadfence();
    }
    __syncthreads();
}

// ---------------------------------------------------------------------------
__global__ void k_count_wprep(const int* __restrict__ dst,
                              const float* W0, const float* W1, const float* W2,
                              const float* W3, const float* W4, const float* W5) {
    int i = blockIdx.x * blockDim.x + threadIdx.x;
    if (i < NE / 2) {
        int2 d = ((const int2*)dst)[i];
        atomicAdd(&g_degi[d.x], 1);
        atomicAdd(&g_degi[d.y], 1);
    }
    if (i < 6 * D * D) {
        int w = i >> 14;
        int r = i & 16383;
        int n = r >> 7, k = r & 127;
        const float* W;
        switch (w) {
            case 0: W = W0; break; case 1: W = W1; break; case 2: W = W2; break;
            case 3: W = W3; break; case 4: W = W4; break; default: W = W5; break;
        }
        float v = W[k * D + n];
        __nv_bfloat16 h = __float2bfloat16_rn(v);
        float res = v - __bfloat162float(h);
        g_Wth[i] = h;
        g_Wtl[i] = __float2bfloat16_rn(res);
    }
}

__global__ void __launch_bounds__(256) k_scan() {
    __shared__ int ws[8];
    __shared__ int s_boff;
    const int b = blockIdx.x;
    const int i = b * 256 + threadIdx.x;
    const int lane = threadIdx.x & 31, wid = threadIdx.x >> 5;

    int v = (i < NN) ? g_degi[i] : 0;
    int x = v;
#pragma unroll
    for (int o = 1; o < 32; o <<= 1) {
        int y = __shfl_up_sync(0xffffffffu, x, o);
        if (lane >= o) x += y;
    }
    if (lane == 31) ws[wid] = x;
    __syncthreads();
    if (wid == 0 && lane < 8) {
        int w = ws[lane];
#pragma unroll
        for (int o = 1; o < 8; o <<= 1) {
            int y = __shfl_up_sync(0xffu, w, o);
            if (lane >= o) w += y;
        }
        ws[lane] = w;
    }
    __syncthreads();
    int off = (wid > 0) ? ws[wid - 1] : 0;
    int S = ws[7];

    if (threadIdx.x == 0) {
        int boff = 0;
        if (b == 0) {
            atomicExch(&g_desc[0], (2ULL << 32) | (unsigned)S);
        } else {
            atomicExch(&g_desc[b], (1ULL << 32) | (unsigned)S);
            int j = b - 1;
            long long sum = 0;
            while (true) {
                unsigned long long d = atomicAdd(&g_desc[j], 0ULL);
                unsigned f = (unsigned)(d >> 32);
                if (f == 0) continue;
                sum += (unsigned)(d & 0xffffffffULL);
                if (f == 2) break;
                j--;
            }
            boff = (int)sum;
            atomicExch(&g_desc[b], (2ULL << 32) | (unsigned)(boff + S));
        }
        s_boff = boff;
    }
    __syncthreads();
    int boff = s_boff;
    if (i < NN) {
        int ex = boff + off + x - v;
        g_rowptr[i] = ex;
        g_cursor[i] = ex;
        g_dinv[i] = 1.0f / fmaxf((float)v, 1.0f);
    }
    if (b == 0 && threadIdx.x == 0) g_rowptr[NN] = NE;
}

__global__ void k_fill(const int* __restrict__ src, const int* __restrict__ dst) {
    int i = blockIdx.x * blockDim.x + threadIdx.x;
    if (i < NE / 2) {
        int2 d = ((const int2*)dst)[i];
        int2 s = ((const int2*)src)[i];
        int p0 = atomicAdd(&g_cursor[d.x], 1);
        g_csrc[p0] = s.x;
        int p1 = atomicAdd(&g_cursor[d.y], 1);
        g_csrc[p1] = s.y;
    }
    if (i < NN) g_degi[i] = 0;
    if (i < SCANB) g_desc[i] = 0ULL;
    if (i < 3) g_tilectr[i] = 0;
    if (i == 3) { g_barcnt = 0u; g_barphase = 0u; }
}

// ---------------------------------------------------------------------------
// one ks-step for a 16x32 warp tile, phased frag loading (bx reused)
// ---------------------------------------------------------------------------
__device__ __forceinline__ void gemm3_step(float acc[4][4],
                                           uint32_t aXH, uint32_t aXL,
                                           uint32_t aWH, uint32_t aWL,
                                           uint32_t aoff,
                                           uint32_t boff0, uint32_t boff1,
                                           uint32_t kb) {
    uint32_t ah[4], al[4], bx[8];
    ldsm4(ah, aXH + aoff + kb);
    ldsm4(bx + 0, aWH + boff0 + kb);
    ldsm4(bx + 4, aWH + boff1 + kb);
#pragma unroll
    for (int j = 0; j < 4; j++)
        mma16816(acc[j], ah, bx + (j >> 1) * 4 + (j & 1) * 2);   // hi*hi
    ldsm4(al, aXL + aoff + kb);
#pragma unroll
    for (int j = 0; j < 4; j++)
        mma16816(acc[j], al, bx + (j >> 1) * 4 + (j & 1) * 2);   // lo*hi
    ldsm4(bx + 0, aWL + boff0 + kb);
    ldsm4(bx + 4, aWL + boff1 + kb);
#pragma unroll
    for (int j = 0; j < 4; j++)
        mma16816(acc[j], ah, bx + (j >> 1) * 4 + (j & 1) * 2);   // hi*lo
}

// ---------------------------------------------------------------------------
// persistent fused 3-layer kernel — 32 warps/SM, async staging
// ---------------------------------------------------------------------------
__global__ void __launch_bounds__(THREADS, 1)
k_layers(const float* __restrict__ feat,
         const float* __restrict__ b1,
         const float* __restrict__ b2,
         const float* __restrict__ b3,
         float* __restrict__ out) {
    extern __shared__ __align__(16) char smem[];
    __shared__ int sRpBuf[2][132];
    __shared__ int s_tile, s_tile2;
    int* sEidx = (int*)(smem + EIDX_OFF);

    const int tid  = threadIdx.x;
    const int wid  = tid >> 5;
    const int lane = tid & 31;
    const int mw = wid >> 2;   // 0..7, 16 rows each
    const int nw = wid & 3;    // 0..3, 32 cols each
    const uint32_t sb = smem_u32(smem);
    const uint32_t sEidx_u = smem_u32(sEidx);

    const int quad = lane >> 3, rin = lane & 7;
    const uint32_t aoff  = (uint32_t)((mw * 16 + (quad & 1) * 8 + rin) * PB + (quad >> 1) * 16);
    const uint32_t boff0 = (uint32_t)((nw * 32 + (quad >> 1) * 8 + rin) * PB + (quad & 1) * 16);
    const uint32_t boff1 = boff0 + 16 * PB;
    const int koff = lane << 2;

    for (int L = 0; L < 3; L++) {
        const float* hin  = (L == 0) ? feat : ((L == 1) ? g_h1 : g_h2);
        float* hout       = (L == 0) ? g_h1 : ((L == 1) ? g_h2 : out);
        const float* bias = (L == 0) ? b1 : ((L == 1) ? b2 : b3);
        const bool relu = (L < 2);
        const __nv_bfloat16* Wh = g_Wth + (size_t)L * 2 * D * D;
        const __nv_bfloat16* Wl = g_Wtl + (size_t)L * 2 * D * D;

        for (int c = tid; c < 2048; c += THREADS) {
            int row = c >> 4, k8 = (c & 15) << 3;
            uint32_t doff = row * PB + k8 * 2;
            *(uint4*)(smem + WSH_OFF + doff) = *(const uint4*)(Wh + row * D + k8);
            *(uint4*)(smem + WSL_OFF + doff) = *(const uint4*)(Wl + row * D + k8);
            *(uint4*)(smem + WNH_OFF + doff) = *(const uint4*)(Wh + 16384 + row * D + k8);
            *(uint4*)(smem + WNL_OFF + doff) = *(const uint4*)(Wl + 16384 + row * D + k8);
        }
        float2 bj[4];
#pragma unroll
        for (int j = 0; j < 4; j++)
            bj[j] = *(const float2*)(bias + nw * 32 + j * 8 + 2 * (lane & 3));

        int pp = 0;

        // prologue: first tile (X + rowptr)
        if (tid == 0) s_tile = atomicAdd(&g_tilectr[L], 1);
        __syncthreads();
        int tile = s_tile;
        if (tile < NTILES) {
            const int nbase = tile * 128;
#pragma unroll
            for (int it = 0; it < 4; it++) {
                int c = tid + it * THREADS;
                int row = c >> 5, kc = (c & 31) << 2;
                int n = nbase + row;
                float4 v = make_float4(0.f, 0.f, 0.f, 0.f);
                if (n < NN) v = *(const float4*)(hin + (size_t)n * D + kc);
                uint2 hi, lo;
                hi.x = split2(v.x, v.y, lo.x);
                hi.y = split2(v.z, v.w, lo.y);
                uint32_t doff = row * PB + kc * 2;
                *(uint2*)(smem + XH_OFF + doff) = hi;
                *(uint2*)(smem + XL_OFF + doff) = lo;
            }
            if (tid <= 128) {
                int n = nbase + tid;
                sRpBuf[0][tid] = g_rowptr[(n < NN) ? n : NN];
            }
        }
        __syncthreads();

        while (tile < NTILES) {
            const int nbase = tile * 128;
            const int* sRp = sRpBuf[pp];
            const int e0base = sRp[0];
            const int ecnt = sRp[128] - e0base;
            const bool inSmem = (ecnt <= EIDX_CAP);

            // ---- pre-GEMM1: next-tile counter + async eidx staging ----
            if (tid == 0) s_tile2 = atomicAdd(&g_tilectr[L], 1);
            if (inSmem) {
                for (int idx = tid; idx < ecnt; idx += THREADS)
                    cpasync4(sEidx_u + idx * 4, g_csrc + e0base + idx);
            }
            cpasync_commit();
            float dvl = 0.f;
            if (lane < 4) {
                int n = nbase + (wid << 2) + lane;
                if (n < NN) dvl = g_dinv[n];
            }

            float acc[4][4];
#pragma unroll
            for (int j = 0; j < 4; j++)
#pragma unroll
                for (int r = 0; r < 4; r++) acc[j][r] = 0.f;

            // ---- GEMM1: X @ Ws (eidx cp.async landing meanwhile) ----
#pragma unroll
            for (int ks = 0; ks < 8; ks++)
                gemm3_step(acc, sb + XH_OFF, sb + XL_OFF, sb + WSH_OFF, sb + WSL_OFF,
                           aoff, boff0, boff1, ks * 32);
            cpasync_wait0();
            __syncthreads();   // (1) GEMM1 X-reads + eidx complete

            // ---- gather: 4 rows/warp, per-node MLP-8, into X buffer ----
            {
                const int r0 = wid << 2;
                const int* __restrict__ idxp =
                    inSmem ? sEidx : (g_csrc + e0base);
#pragma unroll 1
                for (int i = 0; i < 4; i++) {
                    int bgn = sRp[r0 + i] - e0base;
                    int cnt = sRp[r0 + i + 1] - e0base - bgn;
                    float4 a = make_float4(0.f, 0.f, 0.f, 0.f);
                    int e = 0;
                    for (; e + 8 <= cnt; e += 8) {
                        float4 v0 = *(const float4*)(hin + (size_t)idxp[bgn + e + 0] * D + koff);
                        float4 v1 = *(const float4*)(hin + (size_t)idxp[bgn + e + 1] * D + koff);
                        float4 v2 = *(const float4*)(hin + (size_t)idxp[bgn + e + 2] * D + koff);
                        float4 v3 = *(const float4*)(hin + (size_t)idxp[bgn + e + 3] * D + koff);
                        float4 v4 = *(const float4*)(hin + (size_t)idxp[bgn + e + 4] * D + koff);
                        float4 v5 = *(const float4*)(hin + (size_t)idxp[bgn + e + 5] * D + koff);
                        float4 v6 = *(const float4*)(hin + (size_t)idxp[bgn + e + 6] * D + koff);
                        float4 v7 = *(const float4*)(hin + (size_t)idxp[bgn + e + 7] * D + koff);
                        a.x += v0.x + v1.x + v2.x + v3.x + v4.x + v5.x + v6.x + v7.x;
                        a.y += v0.y + v1.y + v2.y + v3.y + v4.y + v5.y + v6.y + v7.y;
                        a.z += v0.z + v1.z + v2.z + v3.z + v4.z + v5.z + v6.z + v7.z;
                        a.w += v0.w + v1.w + v2.w + v3.w + v4.w + v5.w + v6.w + v7.w;
                    }
                    if (e + 4 <= cnt) {
                        float4 v0 = *(const float4*)(hin + (size_t)idxp[bgn + e + 0] * D + koff);
                        float4 v1 = *(const float4*)(hin + (size_t)idxp[bgn + e + 1] * D + koff);
                        float4 v2 = *(const float4*)(hin + (size_t)idxp[bgn + e + 2] * D + koff);
                        float4 v3 = *(const float4*)(hin + (size_t)idxp[bgn + e + 3] * D + koff);
                        a.x += v0.x + v1.x + v2.x + v3.x;
                        a.y += v0.y + v1.y + v2.y + v3.y;
                        a.z += v0.z + v1.z + v2.z + v3.z;
                        a.w += v0.w + v1.w + v2.w + v3.w;
                        e += 4;
                    }
                    if (e + 2 <= cnt) {
                        float4 v0 = *(const float4*)(hin + (size_t)idxp[bgn + e + 0] * D + koff);
                        float4 v1 = *(const float4*)(hin + (size_t)idxp[bgn + e + 1] * D + koff);
                        a.x += v0.x + v1.x; a.y += v0.y + v1.y;
                        a.z += v0.z + v1.z; a.w += v0.w + v1.w;
                        e += 2;
                    }
                    if (e < cnt) {
                        float4 v0 = *(const float4*)(hin + (size_t)idxp[bgn + e] * D + koff);
                        a.x += v0.x; a.y += v0.y; a.z += v0.z; a.w += v0.w;
                    }
                    float di = __shfl_sync(0xffffffffu, dvl, i);
                    uint2 hi, lo;
                    hi.x = split2(a.x * di, a.y * di, lo.x);
                    hi.y = split2(a.z * di, a.w * di, lo.y);
                    uint32_t doff = (r0 + i) * PB + lane * 8;
                    *(uint2*)(smem + XH_OFF + doff) = hi;
                    *(uint2*)(smem + XL_OFF + doff) = lo;
                }
            }
            __syncthreads();   // (2) M complete; s_tile2 visible

            // ---- phase C: prefetch next rowptr (cp.async) + next X (regs),
            //      then GEMM2: M @ Wn ----
            const int ntile = s_tile2;
            const bool nvalid = (ntile < NTILES);
            const int nb2 = ntile * 128;
            if (tid <= 128) {
                int n = nvalid ? (nb2 + tid) : 0;
                if (n > NN) n = NN;
                cpasync4(smem_u32(&sRpBuf[pp ^ 1][tid]), g_rowptr + n);
            }
            cpasync_commit();
            float4 xv[4];
#pragma unroll
            for (int it = 0; it < 4; it++) {
                int c = tid + it * THREADS;
                int row = c >> 5, kc = (c & 31) << 2;
                int n = nb2 + row;
                xv[it] = make_float4(0.f, 0.f, 0.f, 0.f);
                if (nvalid && n < NN)
                    xv[it] = *(const float4*)(hin + (size_t)n * D + kc);
            }
#pragma unroll
            for (int ks = 0; ks < 8; ks++)
                gemm3_step(acc, sb + XH_OFF, sb + XL_OFF, sb + WNH_OFF, sb + WNL_OFF,
                           aoff, boff0, boff1, ks * 32);
            cpasync_wait0();
            __syncthreads();   // (3) M reads done; next rowptr staged

            // ---- epilogue STS ----
            float* sepi = (float*)(smem + XH_OFF);
            {
                int r0e = mw * 16 + (lane >> 2);
#pragma unroll
                for (int j = 0; j < 4; j++) {
                    int col = nw * 32 + j * 8 + 2 * (lane & 3);
                    float2 v0, v1;
                    v0.x = acc[j][0] + bj[j].x;
                    v0.y = acc[j][1] + bj[j].y;
                    v1.x = acc[j][2] + bj[j].x;
                    v1.y = acc[j][3] + bj[j].y;
                    if (relu) {
                        v0.x = fmaxf(v0.x, 0.f); v0.y = fmaxf(v0.y, 0.f);
                        v1.x = fmaxf(v1.x, 0.f); v1.y = fmaxf(v1.y, 0.f);
                    }
                    *(float2*)(sepi + r0e * EPI_PITCH + col) = v0;
                    *(float2*)(sepi + (r0e + 8) * EPI_PITCH + col) = v1;
                }
            }
            __syncthreads();   // (4) epi staged

            // ---- epi STG (coalesced) ----
#pragma unroll
            for (int it = 0; it < 4; it++) {
                int c = tid + it * THREADS;
                int row = c >> 5, k0 = (c & 31) << 2;
                int n = nbase + row;
                if (n < NN) {
                    float4 v = *(const float4*)(sepi + row * EPI_PITCH + k0);
                    *(float4*)(hout + (size_t)n * D + k0) = v;
                }
            }
            __syncthreads();   // (5) sepi reads done

            // ---- stage next X from prefetched regs ----
            if (nvalid) {
#pragma unroll
                for (int it = 0; it < 4; it++) {
                    int c = tid + it * THREADS;
                    int row = c >> 5, kc = (c & 31) << 2;
                    uint2 hi, lo;
                    hi.x = split2(xv[it].x, xv[it].y, lo.x);
                    hi.y = split2(xv[it].z, xv[it].w, lo.y);
                    uint32_t doff = row * PB + kc * 2;
                    *(uint2*)(smem + XH_OFF + doff) = hi;
                    *(uint2*)(smem + XL_OFF + doff) = lo;
                }
            }
            pp ^= 1;
            tile = ntile;
            __syncthreads();   // (6) next X + rowptr ready
        }

        if (L < 2) grid_barrier(L + 1);
    }
}

// ---------------------------------------------------------------------------
extern "C" void kernel_launch(void* const* d_in, const int* in_sizes, int n_in,
                              void* d_out, int out_size) {
    const float* feat = (const float*)d_in[0];
    const int* src = (const int*)d_in[1];
    const int* dst = (const int*)d_in[2];
    const float* Ws1 = (const float*)d_in[3];
    const float* Wn1 = (const float*)d_in[4];
    const float* b1  = (const float*)d_in[5];
    const float* Ws2 = (const float*)d_in[6];
    const float* Wn2 = (const float*)d_in[7];
    const float* b2  = (const float*)d_in[8];
    const float* Ws3 = (const float*)d_in[9];
    const float* Wn3 = (const float*)d_in[10];
    const float* b3  = (const float*)d_in[11];
    float* out = (float*)d_out;

    cudaFuncSetAttribute(k_layers, cudaFuncAttributeMaxDynamicSharedMemorySize, SMEM_BYTES);

    const int EBLK = (NE / 2 + 255) / 256;

    k_count_wprep<<<EBLK, 256>>>(dst, Ws1, Wn1, Ws2, Wn2, Ws3, Wn3);
    k_scan<<<SCANB, 256>>>();
    k_fill<<<EBLK, 256>>>(src, dst);
    k_layers<<<NCTAS, THREADS, SMEM_BYTES>>>(feat, b1, b2, b3, out);
}

// round 14
// speedup vs baseline: 1.9478x; 1.1574x over previous
#include <cuda_runtime.h>
#include <cuda_bf16.h>
#include <cuda_fp16.h>
#include <cstdint>
#include <cstddef>

#define NN 50000
#define NE 600000
#define D  128
#define NTILES ((NN + 127) / 128)   // 391
#define THREADS 1024
#define SCANB ((NN + 255) / 256)    // 196
#define NCTAS 148

#define PB 272
#define XH_OFF 0
#define XL_OFF 34816
#define WS_OFF 69632
#define WN_OFF 104448
#define EIDX_OFF 139264
#define EIDX_CAP 4096
#define SMEM_BYTES (139264 + 16384)   // 155648
#define EPI_PITCH 136

// ---------------------------------------------------------------------------
__device__ float g_h1[(size_t)NN * D];
__device__ float g_h2[(size_t)NN * D];
__device__ int   g_degi[NN];
__device__ float g_dinv[NN];
__device__ int   g_rowptr[NN + 1];
__device__ int   g_cursor[NN];
__device__ int   g_csrc[NE];
__device__ unsigned long long g_desc[SCANB];
__device__ unsigned g_barcnt;
__device__ unsigned g_barphase;
__device__ int g_tilectr[3];
__device__ __half g_Wh[6 * D * D];   // transposed [n][k] fp16 weights

// ---------------------------------------------------------------------------
__device__ __forceinline__ void ldsm4(uint32_t* r, uint32_t addr) {
    asm volatile("ldmatrix.sync.aligned.m8n8.x4.shared.b16 {%0,%1,%2,%3}, [%4];"
                 : "=r"(r[0]), "=r"(r[1]), "=r"(r[2]), "=r"(r[3]) : "r"(addr));
}

__device__ __forceinline__ void mma16816(float* c, const uint32_t* a, const uint32_t* b) {
    asm volatile(
        "mma.sync.aligned.m16n8k16.row.col.f32.f16.f16.f32 "
        "{%0,%1,%2,%3}, {%4,%5,%6,%7}, {%8,%9}, {%0,%1,%2,%3};"
        : "+f"(c[0]), "+f"(c[1]), "+f"(c[2]), "+f"(c[3])
        : "r"(a[0]), "r"(a[1]), "r"(a[2]), "r"(a[3]), "r"(b[0]), "r"(b[1]));
}

__device__ __forceinline__ uint32_t smem_u32(const void* p) {
    return (uint32_t)__cvta_generic_to_shared(p);
}

__device__ __forceinline__ void cpasync4(uint32_t saddr, const void* gaddr) {
    asm volatile("cp.async.ca.shared.global [%0], [%1], 4;"
                 :: "r"(saddr), "l"(gaddr) : "memory");
}
__device__ __forceinline__ void cpasync_commit() {
    asm volatile("cp.async.commit_group;" ::: "memory");
}
__device__ __forceinline__ void cpasync_wait0() {
    asm volatile("cp.async.wait_group 0;" ::: "memory");
}

// fp16 hi/lo split of an fp32 pair: hi = fp16(x), lo = fp16(x - hi)
__device__ __forceinline__ uint32_t split2h(float x, float y, uint32_t& lo) {
    __half2 h = __floats2half2_rn(x, y);
    float2 hf = __half22float2(h);
    __half2 l = __floats2half2_rn(x - hf.x, y - hf.y);
    lo = reinterpret_cast<uint32_t&>(l);
    return reinterpret_cast<uint32_t&>(h);
}

__device__ __forceinline__ void grid_barrier(unsigned gen) {
    __syncthreads();
    if (threadIdx.x == 0) {
        __threadfence();
        unsigned old = atomicAdd(&g_barcnt, 1u);
        if (old == gen * NCTAS - 1u) {
            atomicExch(&g_barphase, gen);
        } else {
            while (atomicAdd(&g_barphase, 0u) < gen) {}
        }
        __threadfence();
    }
    __syncthreads();
}

// ---------------------------------------------------------------------------
__global__ void k_count_wprep(const int* __restrict__ dst,
                              const float* W0, const float* W1, const float* W2,
                              const float* W3, const float* W4, const float* W5) {
    int i = blockIdx.x * blockDim.x + threadIdx.x;
    if (i < NE / 2) {
        int2 d = ((const int2*)dst)[i];
        atomicAdd(&g_degi[d.x], 1);
        atomicAdd(&g_degi[d.y], 1);
    }
    if (i < 6 * D * D) {
        int w = i >> 14;
        int r = i & 16383;
        int n = r >> 7, k = r & 127;
        const float* W;
        switch (w) {
            case 0: W = W0; break; case 1: W = W1; break; case 2: W = W2; break;
            case 3: W = W3; break; case 4: W = W4; break; default: W = W5; break;
        }
        g_Wh[i] = __float2half_rn(W[k * D + n]);
    }
}

__global__ void __launch_bounds__(256) k_scan() {
    __shared__ int ws[8];
    __shared__ int s_boff;
    const int b = blockIdx.x;
    const int i = b * 256 + threadIdx.x;
    const int lane = threadIdx.x & 31, wid = threadIdx.x >> 5;

    int v = (i < NN) ? g_degi[i] : 0;
    int x = v;
#pragma unroll
    for (int o = 1; o < 32; o <<= 1) {
        int y = __shfl_up_sync(0xffffffffu, x, o);
        if (lane >= o) x += y;
    }
    if (lane == 31) ws[wid] = x;
    __syncthreads();
    if (wid == 0 && lane < 8) {
        int w = ws[lane];
#pragma unroll
        for (int o = 1; o < 8; o <<= 1) {
            int y = __shfl_up_sync(0xffu, w, o);
            if (lane >= o) w += y;
        }
        ws[lane] = w;
    }
    __syncthreads();
    int off = (wid > 0) ? ws[wid - 1] : 0;
    int S = ws[7];

    if (threadIdx.x == 0) {
        int boff = 0;
        if (b == 0) {
            atomicExch(&g_desc[0], (2ULL << 32) | (unsigned)S);
        } else {
            atomicExch(&g_desc[b], (1ULL << 32) | (unsigned)S);
            int j = b - 1;
            long long sum = 0;
            while (true) {
                unsigned long long d = atomicAdd(&g_desc[j], 0ULL);
                unsigned f = (unsigned)(d >> 32);
                if (f == 0) continue;
                sum += (unsigned)(d & 0xffffffffULL);
                if (f == 2) break;
                j--;
            }
            boff = (int)sum;
            atomicExch(&g_desc[b], (2ULL << 32) | (unsigned)(boff + S));
        }
        s_boff = boff;
    }
    __syncthreads();
    int boff = s_boff;
    if (i < NN) {
        int ex = boff + off + x - v;
        g_rowptr[i] = ex;
        g_cursor[i] = ex;
        g_dinv[i] = 1.0f / fmaxf((float)v, 1.0f);
    }
    if (b == 0 && threadIdx.x == 0) g_rowptr[NN] = NE;
}

__global__ void k_fill(const int* __restrict__ src, const int* __restrict__ dst) {
    int i = blockIdx.x * blockDim.x + threadIdx.x;
    if (i < NE / 4) {
        int4 d = ((const int4*)dst)[i];
        int4 s = ((const int4*)src)[i];
        int p0 = atomicAdd(&g_cursor[d.x], 1);
        int p1 = atomicAdd(&g_cursor[d.y], 1);
        int p2 = atomicAdd(&g_cursor[d.z], 1);
        int p3 = atomicAdd(&g_cursor[d.w], 1);
        g_csrc[p0] = s.x;
        g_csrc[p1] = s.y;
        g_csrc[p2] = s.z;
        g_csrc[p3] = s.w;
    }
    if (i < NN) g_degi[i] = 0;
    if (i < SCANB) g_desc[i] = 0ULL;
    if (i < 3) g_tilectr[i] = 0;
    if (i == 3) { g_barcnt = 0u; g_barphase = 0u; }
}

// ---------------------------------------------------------------------------
// one ks-step: 2-pass fp16 split (xh*w + xl*w); 4 ldsm4, 8 HMMA
// ---------------------------------------------------------------------------
__device__ __forceinline__ void gemm2_step(float acc[4][4],
                                           uint32_t aXH, uint32_t aXL,
                                           uint32_t aW,
                                           uint32_t aoff,
                                           uint32_t boff0, uint32_t boff1,
                                           uint32_t kb) {
    uint32_t ah[4], al[4], bx[8];
    ldsm4(ah, aXH + aoff + kb);
    ldsm4(bx + 0, aW + boff0 + kb);
    ldsm4(bx + 4, aW + boff1 + kb);
#pragma unroll
    for (int j = 0; j < 4; j++)
        mma16816(acc[j], ah, bx + (j >> 1) * 4 + (j & 1) * 2);   // xh*w
    ldsm4(al, aXL + aoff + kb);
#pragma unroll
    for (int j = 0; j < 4; j++)
        mma16816(acc[j], al, bx + (j >> 1) * 4 + (j & 1) * 2);   // xl*w
}

// ---------------------------------------------------------------------------
// persistent fused 3-layer kernel — 32 warps/SM, fp16 2-pass split
// ---------------------------------------------------------------------------
__global__ void __launch_bounds__(THREADS, 1)
k_layers(const float* __restrict__ feat,
         const float* __restrict__ b1,
         const float* __restrict__ b2,
         const float* __restrict__ b3,
         float* __restrict__ out) {
    extern __shared__ __align__(16) char smem[];
    __shared__ int sRpBuf[2][132];
    __shared__ int s_tile, s_tile2;
    int* sEidx = (int*)(smem + EIDX_OFF);

    const int tid  = threadIdx.x;
    const int wid  = tid >> 5;
    const int lane = tid & 31;
    const int mw = wid >> 2;   // 0..7, 16 rows each
    const int nw = wid & 3;    // 0..3, 32 cols each
    const uint32_t sb = smem_u32(smem);
    const uint32_t sEidx_u = smem_u32(sEidx);

    const int quad = lane >> 3, rin = lane & 7;
    const uint32_t aoff  = (uint32_t)((mw * 16 + (quad & 1) * 8 + rin) * PB + (quad >> 1) * 16);
    const uint32_t boff0 = (uint32_t)((nw * 32 + (quad >> 1) * 8 + rin) * PB + (quad & 1) * 16);
    const uint32_t boff1 = boff0 + 16 * PB;
    const int koff = lane << 2;

    for (int L = 0; L < 3; L++) {
        const float* hin  = (L == 0) ? feat : ((L == 1) ? g_h1 : g_h2);
        float* hout       = (L == 0) ? g_h1 : ((L == 1) ? g_h2 : out);
        const float* bias = (L == 0) ? b1 : ((L == 1) ? b2 : b3);
        const bool relu = (L < 2);
        const __half* Wh = g_Wh + (size_t)L * 2 * D * D;

        // stage Ws + Wn (fp16) into SMEM: 128 rows x 256B = 16 uint4/row
        for (int c = tid; c < 2048; c += THREADS) {
            int row = c >> 4, k8 = (c & 15) << 3;
            uint32_t doff = row * PB + k8 * 2;
            *(uint4*)(smem + WS_OFF + doff) = *(const uint4*)(Wh + row * D + k8);
            *(uint4*)(smem + WN_OFF + doff) = *(const uint4*)(Wh + 16384 + row * D + k8);
        }
        float2 bj[4];
#pragma unroll
        for (int j = 0; j < 4; j++)
            bj[j] = *(const float2*)(bias + nw * 32 + j * 8 + 2 * (lane & 3));

        int pp = 0;

        // prologue: first tile (X + rowptr)
        if (tid == 0) s_tile = atomicAdd(&g_tilectr[L], 1);
        __syncthreads();
        int tile = s_tile;
        if (tile < NTILES) {
            const int nbase = tile * 128;
#pragma unroll
            for (int it = 0; it < 4; it++) {
                int c = tid + it * THREADS;
                int row = c >> 5, kc = (c & 31) << 2;
                int n = nbase + row;
                float4 v = make_float4(0.f, 0.f, 0.f, 0.f);
                if (n < NN) v = *(const float4*)(hin + (size_t)n * D + kc);
                uint2 hi, lo;
                hi.x = split2h(v.x, v.y, lo.x);
                hi.y = split2h(v.z, v.w, lo.y);
                uint32_t doff = row * PB + kc * 2;
                *(uint2*)(smem + XH_OFF + doff) = hi;
                *(uint2*)(smem + XL_OFF + doff) = lo;
            }
            if (tid <= 128) {
                int n = nbase + tid;
                sRpBuf[0][tid] = g_rowptr[(n < NN) ? n : NN];
            }
        }
        __syncthreads();

        while (tile < NTILES) {
            const int nbase = tile * 128;
            const int* sRp = sRpBuf[pp];
            const int e0base = sRp[0];
            const int ecnt = sRp[128] - e0base;
            const bool inSmem = (ecnt <= EIDX_CAP);

            // ---- pre-GEMM1: next-tile counter + async eidx staging ----
            if (tid == 0) s_tile2 = atomicAdd(&g_tilectr[L], 1);
            if (inSmem) {
                for (int idx = tid; idx < ecnt; idx += THREADS)
                    cpasync4(sEidx_u + idx * 4, g_csrc + e0base + idx);
            }
            cpasync_commit();
            float dvl = 0.f;
            if (lane < 4) {
                int n = nbase + (wid << 2) + lane;
                if (n < NN) dvl = g_dinv[n];
            }

            float acc[4][4];
#pragma unroll
            for (int j = 0; j < 4; j++)
#pragma unroll
                for (int r = 0; r < 4; r++) acc[j][r] = 0.f;

            // ---- GEMM1: X @ Ws ----
#pragma unroll
            for (int ks = 0; ks < 8; ks++)
                gemm2_step(acc, sb + XH_OFF, sb + XL_OFF, sb + WS_OFF,
                           aoff, boff0, boff1, ks * 32);
            cpasync_wait0();
            __syncthreads();   // (1) GEMM1 X-reads + eidx complete

            // ---- gather: 4 rows/warp, per-node MLP-8, into X buffer ----
            {
                const int r0 = wid << 2;
                const int* __restrict__ idxp =
                    inSmem ? sEidx : (g_csrc + e0base);
#pragma unroll 1
                for (int i = 0; i < 4; i++) {
                    int bgn = sRp[r0 + i] - e0base;
                    int cnt = sRp[r0 + i + 1] - e0base - bgn;
                    float4 a = make_float4(0.f, 0.f, 0.f, 0.f);
                    int e = 0;
                    for (; e + 8 <= cnt; e += 8) {
                        float4 v0 = *(const float4*)(hin + (size_t)idxp[bgn + e + 0] * D + koff);
                        float4 v1 = *(const float4*)(hin + (size_t)idxp[bgn + e + 1] * D + koff);
                        float4 v2 = *(const float4*)(hin + (size_t)idxp[bgn + e + 2] * D + koff);
                        float4 v3 = *(const float4*)(hin + (size_t)idxp[bgn + e + 3] * D + koff);
                        float4 v4 = *(const float4*)(hin + (size_t)idxp[bgn + e + 4] * D + koff);
                        float4 v5 = *(const float4*)(hin + (size_t)idxp[bgn + e + 5] * D + koff);
                        float4 v6 = *(const float4*)(hin + (size_t)idxp[bgn + e + 6] * D + koff);
                        float4 v7 = *(const float4*)(hin + (size_t)idxp[bgn + e + 7] * D + koff);
                        a.x += v0.x + v1.x + v2.x + v3.x + v4.x + v5.x + v6.x + v7.x;
                        a.y += v0.y + v1.y + v2.y + v3.y + v4.y + v5.y + v6.y + v7.y;
                        a.z += v0.z + v1.z + v2.z + v3.z + v4.z + v5.z + v6.z + v7.z;
                        a.w += v0.w + v1.w + v2.w + v3.w + v4.w + v5.w + v6.w + v7.w;
                    }
                    if (e + 4 <= cnt) {
                        float4 v0 = *(const float4*)(hin + (size_t)idxp[bgn + e + 0] * D + koff);
                        float4 v1 = *(const float4*)(hin + (size_t)idxp[bgn + e + 1] * D + koff);
                        float4 v2 = *(const float4*)(hin + (size_t)idxp[bgn + e + 2] * D + koff);
                        float4 v3 = *(const float4*)(hin + (size_t)idxp[bgn + e + 3] * D + koff);
                        a.x += v0.x + v1.x + v2.x + v3.x;
                        a.y += v0.y + v1.y + v2.y + v3.y;
                        a.z += v0.z + v1.z + v2.z + v3.z;
                        a.w += v0.w + v1.w + v2.w + v3.w;
                        e += 4;
                    }
                    if (e + 2 <= cnt) {
                        float4 v0 = *(const float4*)(hin + (size_t)idxp[bgn + e + 0] * D + koff);
                        float4 v1 = *(const float4*)(hin + (size_t)idxp[bgn + e + 1] * D + koff);
                        a.x += v0.x + v1.x; a.y += v0.y + v1.y;
                        a.z += v0.z + v1.z; a.w += v0.w + v1.w;
                        e += 2;
                    }
                    if (e < cnt) {
                        float4 v0 = *(const float4*)(hin + (size_t)idxp[bgn + e] * D + koff);
                        a.x += v0.x; a.y += v0.y; a.z += v0.z; a.w += v0.w;
                    }
                    float di = __shfl_sync(0xffffffffu, dvl, i);
                    uint2 hi, lo;
                    hi.x = split2h(a.x * di, a.y * di, lo.x);
                    hi.y = split2h(a.z * di, a.w * di, lo.y);
                    uint32_t doff = (r0 + i) * PB + lane * 8;
                    *(uint2*)(smem + XH_OFF + doff) = hi;
                    *(uint2*)(smem + XL_OFF + doff) = lo;
                }
            }
            __syncthreads();   // (2) M complete; s_tile2 visible

            // ---- phase C: prefetch next rowptr + next X, then GEMM2 ----
            const int ntile = s_tile2;
            const bool nvalid = (ntile < NTILES);
            const int nb2 = ntile * 128;
            if (tid <= 128) {
                int n = nvalid ? (nb2 + tid) : 0;
                if (n > NN) n = NN;
                cpasync4(smem_u32(&sRpBuf[pp ^ 1][tid]), g_rowptr + n);
            }
            cpasync_commit();
            float4 xv[4];
#pragma unroll
            for (int it = 0; it < 4; it++) {
                int c = tid + it * THREADS;
                int row = c >> 5, kc = (c & 31) << 2;
                int n = nb2 + row;
                xv[it] = make_float4(0.f, 0.f, 0.f, 0.f);
                if (nvalid && n < NN)
                    xv[it] = *(const float4*)(hin + (size_t)n * D + kc);
            }
#pragma unroll
            for (int ks = 0; ks < 8; ks++)
                gemm2_step(acc, sb + XH_OFF, sb + XL_OFF, sb + WN_OFF,
                           aoff, boff0, boff1, ks * 32);
            cpasync_wait0();
            __syncthreads();   // (3) M reads done; next rowptr staged

            // ---- epilogue STS ----
            float* sepi = (float*)(smem + XH_OFF);
            {
                int r0e = mw * 16 + (lane >> 2);
#pragma unroll
                for (int j = 0; j < 4; j++) {
                    int col = nw * 32 + j * 8 + 2 * (lane & 3);
                    float2 v0, v1;
                    v0.x = acc[j][0] + bj[j].x;
                    v0.y = acc[j][1] + bj[j].y;
                    v1.x = acc[j][2] + bj[j].x;
                    v1.y = acc[j][3] + bj[j].y;
                    if (relu) {
                        v0.x = fmaxf(v0.x, 0.f); v0.y = fmaxf(v0.y, 0.f);
                        v1.x = fmaxf(v1.x, 0.f); v1.y = fmaxf(v1.y, 0.f);
                    }
                    *(float2*)(sepi + r0e * EPI_PITCH + col) = v0;
                    *(float2*)(sepi + (r0e + 8) * EPI_PITCH + col) = v1;
                }
            }
            __syncthreads();   // (4) epi staged

            // ---- epi STG (coalesced) ----
#pragma unroll
            for (int it = 0; it < 4; it++) {
                int c = tid + it * THREADS;
                int row = c >> 5, k0 = (c & 31) << 2;
                int n = nbase + row;
                if (n < NN) {
                    float4 v = *(const float4*)(sepi + row * EPI_PITCH + k0);
                    *(float4*)(hout + (size_t)n * D + k0) = v;
                }
            }
            __syncthreads();   // (5) sepi reads done

            // ---- stage next X from prefetched regs ----
            if (nvalid) {
#pragma unroll
                for (int it = 0; it < 4; it++) {
                    int c = tid + it * THREADS;
                    int row = c >> 5, kc = (c & 31) << 2;
                    uint2 hi, lo;
                    hi.x = split2h(xv[it].x, xv[it].y, lo.x);
                    hi.y = split2h(xv[it].z, xv[it].w, lo.y);
                    uint32_t doff = row * PB + kc * 2;
                    *(uint2*)(smem + XH_OFF + doff) = hi;
                    *(uint2*)(smem + XL_OFF + doff) = lo;
                }
            }
            pp ^= 1;
            tile = ntile;
            __syncthreads();   // (6) next X + rowptr ready
        }

        if (L < 2) grid_barrier(L + 1);
    }
}

// ---------------------------------------------------------------------------
extern "C" void kernel_launch(void* const* d_in, const int* in_sizes, int n_in,
                              void* d_out, int out_size) {
    const float* feat = (const float*)d_in[0];
    const int* src = (const int*)d_in[1];
    const int* dst = (const int*)d_in[2];
    const float* Ws1 = (const float*)d_in[3];
    const float* Wn1 = (const float*)d_in[4];
    const float* b1  = (const float*)d_in[5];
    const float* Ws2 = (const float*)d_in[6];
    const float* Wn2 = (const float*)d_in[7];
    const float* b2  = (const float*)d_in[8];
    const float* Ws3 = (const float*)d_in[9];
    const float* Wn3 = (const float*)d_in[10];
    const float* b3  = (const float*)d_in[11];
    float* out = (float*)d_out;

    cudaFuncSetAttribute(k_layers, cudaFuncAttributeMaxDynamicSharedMemorySize, SMEM_BYTES);

    const int EBLK  = (NE / 2 + 255) / 256;
    const int EBLK4 = (NE / 4 + 255) / 256;

    k_count_wprep<<<EBLK, 256>>>(dst, Ws1, Wn1, Ws2, Wn2, Ws3, Wn3);
    k_scan<<<SCANB, 256>>>();
    k_fill<<<EBLK4, 256>>>(src, dst);
    k_layers<<<NCTAS, THREADS, SMEM_BYTES>>>(feat, b1, b2, b3, out);
}